// round 14
// baseline (speedup 1.0000x reference)
#include <cuda_runtime.h>
#include <cuda_bf16.h>
#include <math.h>
#include <float.h>
#include <stdint.h>

// Problem dims
#define BATCH 64
#define NN    10000
#define NC    201
#define H     64
#define ND    128      // node feature dim (2H)
#define HA    256      // actor/critic hidden
#define NCH   9        // chunks per batch (wmma featpool)
#define TPT   9        // 128-node tiles per chunk (9*9*128 = 10368 >= 10000, predicated)
#define CC    32       // candidates per actor block
#define NCHUNK 7       // ceil(201/32)

// Scratch (device globals: no allocation allowed)
__device__ float g_psum[BATCH][NCH][ND];
__device__ float g_pmax[BATCH][NCH][ND];
__device__ float g_pooled[BATCH][2 * ND];
__device__ float g_pproj[BATCH][HA];
__device__ float g_scores[BATCH][NC];
__device__ int   g_mask_i32;
// Pre-split bf16 fragment-packed actor weights: (bh0, bh1, bl0, bl1) per lane.
__device__ uint4 g_awf1[8 * 32 * 32];    // [kc 8][ntg 32][lane 32]   (k=128)
__device__ uint4 g_awf2[16 * 32 * 32];   // [kc 16][ntg 32][lane 32]  (k=256)

// ---- f32x2 packed helpers ----
static __device__ __forceinline__ unsigned long long dup2(float w) {
    unsigned long long r;
    unsigned int b = __float_as_uint(w);
    asm("mov.b64 %0, {%1, %1};" : "=l"(r) : "r"(b));
    return r;
}
static __device__ __forceinline__ unsigned long long pk2(float lo, float hi) {
    unsigned long long r;
    unsigned int a = __float_as_uint(lo), b = __float_as_uint(hi);
    asm("mov.b64 %0, {%1, %2};" : "=l"(r) : "r"(a), "r"(b));
    return r;
}
static __device__ __forceinline__ unsigned long long fma2(
    unsigned long long a, unsigned long long b, unsigned long long c) {
    unsigned long long d;
    asm("fma.rn.f32x2 %0, %1, %2, %3;" : "=l"(d) : "l"(a), "l"(b), "l"(c));
    return d;
}
static __device__ __forceinline__ void unpack2(unsigned long long v, float& lo, float& hi) {
    unsigned int a, b;
    asm("mov.b64 {%0, %1}, %2;" : "=r"(a), "=r"(b) : "l"(v));
    lo = __uint_as_float(a);
    hi = __uint_as_float(b);
}

// ---- bf16 split/pack + warp-MMA helpers (sm_80+ generic) ----
static __device__ __forceinline__ void split_bf16(float f, __nv_bfloat16& h, __nv_bfloat16& l) {
    h = __float2bfloat16_rn(f);
    l = __float2bfloat16_rn(f - __bfloat162float(h));
}
static __device__ __forceinline__ uint32_t pack_bf162(__nv_bfloat16 e0, __nv_bfloat16 e1) {
    __nv_bfloat162 v = __halves2bfloat162(e0, e1);   // .x = e0 (low 16 bits)
    return *reinterpret_cast<uint32_t*>(&v);
}
static __device__ __forceinline__ void split_pack2(float f0, float f1,
                                                   uint32_t& hp, uint32_t& lp) {
    __nv_bfloat16 h0, l0, h1, l1;
    split_bf16(f0, h0, l0);
    split_bf16(f1, h1, l1);
    hp = pack_bf162(h0, h1);
    lp = pack_bf162(l0, l1);
}
static __device__ __forceinline__ void hmma_bf16(
    float* d, const uint4& a, uint32_t b0, uint32_t b1) {
    asm volatile(
        "mma.sync.aligned.m16n8k16.row.col.f32.bf16.bf16.f32 "
        "{%0,%1,%2,%3}, {%4,%5,%6,%7}, {%8,%9}, {%0,%1,%2,%3};"
        : "+f"(d[0]), "+f"(d[1]), "+f"(d[2]), "+f"(d[3])
        : "r"(a.x), "r"(a.y), "r"(a.z), "r"(a.w), "r"(b0), "r"(b1));
}

// ---------------------------------------------------------------------------
// K0: weight pre-split (all blocks) + mask-dtype sniff (block 0, warp 0).
// ---------------------------------------------------------------------------
__global__ __launch_bounds__(256) void k_wsplit(
    const float* __restrict__ aw1, const float* __restrict__ aw2,
    const unsigned char* __restrict__ m)
{
    if (blockIdx.x == 0 && threadIdx.x < 32) {
        int any = 0;
        for (int i = threadIdx.x; i < 1024; i += 32)
            if ((i & 3) && m[i]) any = 1;
        const unsigned bal = __ballot_sync(0xffffffffu, any);
        if (threadIdx.x == 0) g_mask_i32 = bal ? 0 : 1;
    }

    const int t = blockIdx.x * 256 + threadIdx.x;
    const int n1 = 8 * 32 * 32;
    if (t < n1) {
        const int lane = t & 31, ntg = (t >> 5) & 31, kc = t >> 10;
        const int g = lane >> 2, tg = lane & 3;
        const int j = ntg * 8 + g;
        const int k0 = kc * 16 + 2 * tg;
        __nv_bfloat16 h00, l00, h01, l01, h10, l10, h11, l11;
        split_bf16(aw1[(k0 + 0) * HA + j], h00, l00);
        split_bf16(aw1[(k0 + 1) * HA + j], h01, l01);
        split_bf16(aw1[(k0 + 8) * HA + j], h10, l10);
        split_bf16(aw1[(k0 + 9) * HA + j], h11, l11);
        uint4 v;
        v.x = pack_bf162(h00, h01);
        v.y = pack_bf162(h10, h11);
        v.z = pack_bf162(l00, l01);
        v.w = pack_bf162(l10, l11);
        g_awf1[t] = v;
    } else {
        const int t2 = t - n1;
        if (t2 >= 16 * 32 * 32) return;
        const int lane = t2 & 31, ntg = (t2 >> 5) & 31, kc = t2 >> 10;
        const int g = lane >> 2, tg = lane & 3;
        const int j = ntg * 8 + g;
        const int k0 = kc * 16 + 2 * tg;
        __nv_bfloat16 h00, l00, h01, l01, h10, l10, h11, l11;
        split_bf16(aw2[(k0 + 0) * HA + j], h00, l00);
        split_bf16(aw2[(k0 + 1) * HA + j], h01, l01);
        split_bf16(aw2[(k0 + 8) * HA + j], h10, l10);
        split_bf16(aw2[(k0 + 9) * HA + j], h11, l11);
        uint4 v;
        v.x = pack_bf162(h00, h01);
        v.y = pack_bf162(h10, h11);
        v.z = pack_bf162(l00, l01);
        v.w = pack_bf162(l10, l11);
        g_awf2[t2] = v;
    }
}

// layer-1 tile -> bf16 A-fragment layout (hi/lo). Indices identical to the
// proven R12 code. AH/AL are u32* bases; XB is the s_x4 buffer index.
#define FP_LAYER1(AH, AL, XB)                                                  \
    do {                                                                       \
        _Pragma("unroll")                                                      \
        for (int q = 0; q < 16; q++) {                                         \
            const int s = q * 256 + tid;                                       \
            const int r = s & 3;                                               \
            const int ln = (s >> 2) & 31;                                      \
            const int kc = (s >> 7) & 3;                                       \
            const int mt = s >> 9;                                             \
            const int row = mt * 16 + (ln >> 2) + (r & 1) * 8;                 \
            const int k0 = kc * 16 + 2 * (ln & 3) + ((r >> 1) & 1) * 8;        \
            const float4 xv = s_x4[XB][row];                                   \
            const float4 wa = *(const float4*)&s_w1t[k0][0];                   \
            const float4 wb = *(const float4*)&s_w1t[k0 + 1][0];               \
            const float h0 = fmaxf(fmaf(xv.x, wa.x,                            \
                fmaf(xv.y, wa.y, fmaf(xv.z, wa.z, wa.w))), 0.f);               \
            const float h1 = fmaxf(fmaf(xv.x, wb.x,                            \
                fmaf(xv.y, wb.y, fmaf(xv.z, wb.z, wb.w))), 0.f);               \
            uint32_t hp, lp;                                                   \
            split_pack2(h0, h1, hp, lp);                                       \
            const int addr = (mt * 4 + kc) * 128 + ln * 4 + r;                 \
            (AH)[addr] = hp;                                                   \
            (AL)[addr] = lp;                                                   \
        }                                                                      \
    } while (0)

// ---------------------------------------------------------------------------
// K1: featpool via 3-term bf16 split MMA, software-pipelined (inline, no
// lambdas). Double-buffered A fragments + x tile; ONE __syncthreads per tile:
//   iter t: [load x(t+1) -> s_x4[pn]]; sync; MMA+fold(t) from A[pb];
//           [layer1(t+1) -> A[pn]].
// Hazards: every buffer write is separated from its previous readers by
// exactly one barrier (verified for both A and x buffers).
// ---------------------------------------------------------------------------
__global__ __launch_bounds__(256) void k_featpool_wmma(
    const float* __restrict__ x,
    const float* __restrict__ w1, const float* __restrict__ b1,
    const float* __restrict__ w2, const float* __restrict__ b2)
{
    extern __shared__ __align__(16) uint32_t s_dyn[];
    // buffer p: Ah at p*8192, Al at p*8192 + 4096 (u32 units); total 16384 u32
    __shared__ __align__(16) float4 s_x4[2][128];
    __shared__ __align__(16) float s_w1t[H][4];

    const int tid = threadIdx.x;
    const int wid = tid >> 5, lane = tid & 31;
    const int b = blockIdx.y, chunk = blockIdx.x;
    const int base = chunk * TPT * 128;
    const int tig = lane & 3;
    const int gid = lane >> 2;

    if (tid < H) {
        s_w1t[tid][0] = w1[tid];
        s_w1t[tid][1] = w1[H + tid];
        s_w1t[tid][2] = w1[2 * H + tid];
        s_w1t[tid][3] = b1[tid];
    }

    // B fragments: w2[k][d] (k-major). Per (kc 4, nt 2): 2 hi + 2 lo regs.
    uint32_t Bh[4][2][2], Bl[4][2][2];
#pragma unroll
    for (int kc = 0; kc < 4; kc++)
#pragma unroll
        for (int nt = 0; nt < 2; nt++) {
            const int d = 16 * wid + nt * 8 + gid;
            const int k0 = kc * 16 + 2 * tig;
            __nv_bfloat16 h0, l0, h1, l1;
            split_bf16(__ldg(w2 + (k0 + 0) * ND + d), h0, l0);
            split_bf16(__ldg(w2 + (k0 + 1) * ND + d), h1, l1);
            Bh[kc][nt][0] = pack_bf162(h0, h1);
            Bl[kc][nt][0] = pack_bf162(l0, l1);
            split_bf16(__ldg(w2 + (k0 + 8) * ND + d), h0, l0);
            split_bf16(__ldg(w2 + (k0 + 9) * ND + d), h1, l1);
            Bh[kc][nt][1] = pack_bf162(h0, h1);
            Bl[kc][nt][1] = pack_bf162(l0, l1);
        }

    float bcol[2][2];
#pragma unroll
    for (int nt = 0; nt < 2; nt++) {
        const int d0 = 16 * wid + nt * 8 + 2 * tig;
        bcol[nt][0] = b2[d0];
        bcol[nt][1] = b2[d0 + 1];
    }

    float psum[2][4], pmax[2][4];
#pragma unroll
    for (int nt = 0; nt < 2; nt++)
#pragma unroll
        for (int e = 0; e < 4; e++) { psum[nt][e] = 0.f; pmax[nt][e] = 0.f; }

    // ---- prologue: x(0) -> s_x4[0]; layer1(0) -> A[0] ----
    if (tid < 128) {
        const int node = base + tid;
        float4 xv = make_float4(0.f, 0.f, 0.f, 0.f);
        if (node < NN) {
            const float* xp = x + ((long)b * NN + node) * 3;
            xv.x = xp[0]; xv.y = xp[1]; xv.z = xp[2];
        }
        s_x4[0][tid] = xv;
    }
    __syncthreads();
    {
        uint32_t* Ah = s_dyn;
        uint32_t* Al = s_dyn + 4096;
        FP_LAYER1(Ah, Al, 0);
    }

    // ---- pipelined main loop: one sync per tile ----
    for (int t = 0; t < TPT; t++) {
        const int pb = t & 1, pn = pb ^ 1;

        if (t + 1 < TPT && tid < 128) {
            const int node = base + (t + 1) * 128 + tid;
            float4 xv = make_float4(0.f, 0.f, 0.f, 0.f);
            if (node < NN) {
                const float* xp = x + ((long)b * NN + node) * 3;
                xv.x = xp[0]; xv.y = xp[1]; xv.z = xp[2];
            }
            s_x4[pn][tid] = xv;
        }
        __syncthreads();   // A[pb] + s_x4[pn] visible; A[pn]/x[pn] old reads done

        // MMA (3-term bf16) + predicated pooling fold from A[pb]
        {
            const uint32_t* Ah = s_dyn + pb * 8192;
            const uint32_t* Al = Ah + 4096;
            for (int mt = 0; mt < 8; mt++) {
                float d[2][4];
#pragma unroll
                for (int nt = 0; nt < 2; nt++)
#pragma unroll
                    for (int e = 0; e < 4; e++) d[nt][e] = 0.f;
#pragma unroll
                for (int kc = 0; kc < 4; kc++) {
                    const int off = (mt * 4 + kc) * 128 + lane * 4;
                    const uint4 ah = *(const uint4*)&Ah[off];
                    const uint4 al = *(const uint4*)&Al[off];
#pragma unroll
                    for (int nt = 0; nt < 2; nt++) {
                        hmma_bf16(d[nt], ah, Bh[kc][nt][0], Bh[kc][nt][1]);
                        hmma_bf16(d[nt], ah, Bl[kc][nt][0], Bl[kc][nt][1]);
                        hmma_bf16(d[nt], al, Bh[kc][nt][0], Bh[kc][nt][1]);
                    }
                }
                const int r0 = base + t * 128 + mt * 16 + gid;
                const bool v0 = r0 < NN;
                const bool v1 = (r0 + 8) < NN;
#pragma unroll
                for (int nt = 0; nt < 2; nt++) {
                    if (v0) {
                        const float y0 = fmaxf(d[nt][0] + bcol[nt][0], 0.f);
                        const float y1 = fmaxf(d[nt][1] + bcol[nt][1], 0.f);
                        psum[nt][0] += y0; pmax[nt][0] = fmaxf(pmax[nt][0], y0);
                        psum[nt][1] += y1; pmax[nt][1] = fmaxf(pmax[nt][1], y1);
                    }
                    if (v1) {
                        const float y2 = fmaxf(d[nt][2] + bcol[nt][0], 0.f);
                        const float y3 = fmaxf(d[nt][3] + bcol[nt][1], 0.f);
                        psum[nt][2] += y2; pmax[nt][2] = fmaxf(pmax[nt][2], y2);
                        psum[nt][3] += y3; pmax[nt][3] = fmaxf(pmax[nt][3], y3);
                    }
                }
            }
        }

        // layer1(t+1) -> A[pn] (overlaps tensor-pipe work across warps)
        if (t + 1 < TPT) {
            uint32_t* Ah = s_dyn + pn * 8192;
            uint32_t* Al = Ah + 4096;
            if (pn) {
                FP_LAYER1(Ah, Al, 1);
            } else {
                FP_LAYER1(Ah, Al, 0);
            }
        }
    }

#pragma unroll
    for (int nt = 0; nt < 2; nt++) {
        float sc0 = psum[nt][0] + psum[nt][2];
        float sc1 = psum[nt][1] + psum[nt][3];
        float mc0 = fmaxf(pmax[nt][0], pmax[nt][2]);
        float mc1 = fmaxf(pmax[nt][1], pmax[nt][3]);
#pragma unroll
        for (int ofs = 4; ofs <= 16; ofs <<= 1) {
            sc0 += __shfl_xor_sync(0xffffffffu, sc0, ofs);
            sc1 += __shfl_xor_sync(0xffffffffu, sc1, ofs);
            mc0 = fmaxf(mc0, __shfl_xor_sync(0xffffffffu, mc0, ofs));
            mc1 = fmaxf(mc1, __shfl_xor_sync(0xffffffffu, mc1, ofs));
        }
        if (lane < 4) {
            const int d0 = 16 * wid + nt * 8 + 2 * lane;
            g_psum[b][chunk][d0]     = sc0;
            g_psum[b][chunk][d0 + 1] = sc1;
            g_pmax[b][chunk][d0]     = mc0;
            g_pmax[b][chunk][d0 + 1] = mc1;
        }
    }
}

// ---------------------------------------------------------------------------
// K1b: combine partials -> pooled + pproj.
// ---------------------------------------------------------------------------
__global__ __launch_bounds__(HA) void k_pool(const float* __restrict__ aw1) {
    __shared__ float s_pool[2 * ND];
    const int b = blockIdx.x, tid = threadIdx.x;
    if (tid < ND) {
        float s = 0.f, m = 0.f;
#pragma unroll
        for (int ch = 0; ch < NCH; ch++) {
            s += g_psum[b][ch][tid];
            m = fmaxf(m, g_pmax[b][ch][tid]);
        }
        const float mean = s * (1.f / NN);
        g_pooled[b][tid] = mean;
        g_pooled[b][ND + tid] = m;
        s_pool[tid] = mean;
        s_pool[ND + tid] = m;
    }
    __syncthreads();
    float pc = 0.f;
    for (int i = 0; i < 2 * ND; i++)
        pc = fmaf(s_pool[i], __ldg(aw1 + (ND + i) * HA + tid), pc);
    g_pproj[b][tid] = pc;
}

// ---------------------------------------------------------------------------
// K2: actor via 3-term bf16 split MMA (R12, proven).
// ---------------------------------------------------------------------------
__global__ __launch_bounds__(256, 2) void k_actor_mma(
    const float* __restrict__ x, const int* __restrict__ cand,
    const float* __restrict__ fw1, const float* __restrict__ fb1,
    const float* __restrict__ fw2, const float* __restrict__ fb2,
    const float* __restrict__ ab1, const float* __restrict__ ab2,
    const float* __restrict__ aw3, const float* __restrict__ ab3)
{
    extern __shared__ __align__(16) uint32_t sA[];
    uint32_t* s_fA  = sA;              // 2048
    uint32_t* s_fAl = sA + 2048;       // 2048
    uint32_t* s_mA  = sA + 4096;       // 4096
    uint32_t* s_mAl = sA + 8192;       // 4096
    float* s_hT  = (float*)(sA + 12288);   // 2048 (64 k x 32 c)
    float* s_x   = s_hT + 2048;            // 96
    float* s_w1t = s_x + 96;               // 256
    float* s_red = s_w1t + 256;            // 256

    const int tid = threadIdx.x;
    const int w = tid >> 5, lane = tid & 31;
    const int gid = lane >> 2, tig = lane & 3;
    const int b = blockIdx.y;
    const int c0 = blockIdx.x * CC;
    const int nvalid = min(CC, NC - c0);

    if (tid < H) {
        s_w1t[tid * 4 + 0] = fw1[tid];
        s_w1t[tid * 4 + 1] = fw1[H + tid];
        s_w1t[tid * 4 + 2] = fw1[2 * H + tid];
        s_w1t[tid * 4 + 3] = fb1[tid];
    }
    if (tid < CC * 3) {
        const int c = tid / 3, i = tid - c * 3;
        float v = 0.f;
        if (c < nvalid) {
            const int node = cand[b * NC + c0 + c];
            v = x[((long)b * NN + node) * 3 + i];
        }
        s_x[tid] = v;
    }
    __syncthreads();

    // fe layer 1 -> s_hT[k][c]
    {
        const int n1 = tid & 31, kg = tid >> 5;
        const float x0 = s_x[n1 * 3 + 0];
        const float x1 = s_x[n1 * 3 + 1];
        const float x2 = s_x[n1 * 3 + 2];
#pragma unroll
        for (int m = 0; m < 8; m++) {
            const int k = kg * 8 + m;
            const float4 wv = *(const float4*)&s_w1t[k * 4];
            const float v = fmaf(x0, wv.x, fmaf(x1, wv.y, fmaf(x2, wv.z, wv.w)));
            s_hT[k * CC + n1] = fmaxf(v, 0.f);
        }
    }
    __syncthreads();

    // fe layer 2 -> feat fragments
    {
        const int dg = tid & 63, qh = tid >> 6;
        const int d0 = 2 * dg;
        unsigned long long a2[8];
#pragma unroll
        for (int i = 0; i < 8; i++) a2[i] = 0ull;
#pragma unroll 4
        for (int k = 0; k < H; k++) {
            const float2 wp = __ldg((const float2*)(fw2 + k * ND + d0));
            const unsigned long long wpk = pk2(wp.x, wp.y);
            const float4 hA = *(const float4*)(s_hT + k * CC + qh * 8);
            const float4 hB = *(const float4*)(s_hT + k * CC + qh * 8 + 4);
            a2[0] = fma2(dup2(hA.x), wpk, a2[0]);
            a2[1] = fma2(dup2(hA.y), wpk, a2[1]);
            a2[2] = fma2(dup2(hA.z), wpk, a2[2]);
            a2[3] = fma2(dup2(hA.w), wpk, a2[3]);
            a2[4] = fma2(dup2(hB.x), wpk, a2[4]);
            a2[5] = fma2(dup2(hB.y), wpk, a2[5]);
            a2[6] = fma2(dup2(hB.z), wpk, a2[6]);
            a2[7] = fma2(dup2(hB.w), wpk, a2[7]);
        }
        const float b20 = fb2[d0], b21 = fb2[d0 + 1];
        const int kc = d0 >> 4;
        const int t2 = (d0 >> 1) & 3;
        const int r2 = ((d0 >> 3) & 1) * 2;
#pragma unroll
        for (int i = 0; i < 8; i++) {
            const int c = qh * 8 + i;
            float lo, hi;
            unpack2(a2[i], lo, hi);
            const float y0 = fmaxf(lo + b20, 0.f);
            const float y1 = fmaxf(hi + b21, 0.f);
            uint32_t hp, lp;
            split_pack2(y0, y1, hp, lp);
            const int rit = c & 15;
            const int addr = ((c >> 4) * 8 + kc) * 128 +
                             ((rit & 7) * 4 + t2) * 4 + (rit >> 3) + r2;
            s_fA[addr] = hp;
            s_fAl[addr] = lp;
        }
    }

    float bj1[4][2], bj2v[4][2], w3j[4][2];
#pragma unroll
    for (int nt = 0; nt < 4; nt++) {
        const int j0 = (4 * w + nt) * 8 + 2 * tig;
        bj1[nt][0] = ab1[j0] + g_pproj[b][j0];
        bj1[nt][1] = ab1[j0 + 1] + g_pproj[b][j0 + 1];
        bj2v[nt][0] = ab2[j0];     bj2v[nt][1] = ab2[j0 + 1];
        w3j[nt][0] = aw3[j0];      w3j[nt][1] = aw3[j0 + 1];
    }
    __syncthreads();

    float acc[2][4][4];

    // ---- layer 1 MMA: kc = 0..7 ----
#pragma unroll
    for (int mt = 0; mt < 2; mt++)
#pragma unroll
        for (int nt = 0; nt < 4; nt++)
#pragma unroll
            for (int e = 0; e < 4; e++) acc[mt][nt][e] = 0.f;

#pragma unroll 2
    for (int kc = 0; kc < 8; kc++) {
        const uint4 ah0 = *(const uint4*)&s_fA[kc * 128 + lane * 4];
        const uint4 al0 = *(const uint4*)&s_fAl[kc * 128 + lane * 4];
        const uint4 ah1 = *(const uint4*)&s_fA[(8 + kc) * 128 + lane * 4];
        const uint4 al1 = *(const uint4*)&s_fAl[(8 + kc) * 128 + lane * 4];
#pragma unroll
        for (int nt = 0; nt < 4; nt++) {
            const uint4 bf = __ldg(&g_awf1[(kc * 32 + 4 * w + nt) * 32 + lane]);
            hmma_bf16(acc[0][nt], ah0, bf.x, bf.y);
            hmma_bf16(acc[0][nt], ah0, bf.z, bf.w);
            hmma_bf16(acc[0][nt], al0, bf.x, bf.y);
            hmma_bf16(acc[1][nt], ah1, bf.x, bf.y);
            hmma_bf16(acc[1][nt], ah1, bf.z, bf.w);
            hmma_bf16(acc[1][nt], al1, bf.x, bf.y);
        }
    }

    // layer-1 epilogue: tanh -> mid fragments
#pragma unroll
    for (int mt = 0; mt < 2; mt++)
#pragma unroll
        for (int nt = 0; nt < 4; nt++) {
            const int ntg = 4 * w + nt;
            const int kc2 = ntg >> 1;
            const int r2 = (ntg & 1) * 2;
            const int base = (mt * 16 + kc2) * 128 + (gid * 4 + tig) * 4 + r2;
            const float v0 = tanhf(acc[mt][nt][0] + bj1[nt][0]);
            const float v1 = tanhf(acc[mt][nt][1] + bj1[nt][1]);
            const float v2 = tanhf(acc[mt][nt][2] + bj1[nt][0]);
            const float v3 = tanhf(acc[mt][nt][3] + bj1[nt][1]);
            uint32_t hp, lp;
            split_pack2(v0, v1, hp, lp);
            s_mA[base] = hp;     s_mAl[base] = lp;
            split_pack2(v2, v3, hp, lp);
            s_mA[base + 1] = hp; s_mAl[base + 1] = lp;
        }
    __syncthreads();

    // ---- layer 2 MMA: kc = 0..15 ----
#pragma unroll
    for (int mt = 0; mt < 2; mt++)
#pragma unroll
        for (int nt = 0; nt < 4; nt++)
#pragma unroll
            for (int e = 0; e < 4; e++) acc[mt][nt][e] = 0.f;

#pragma unroll 2
    for (int kc = 0; kc < 16; kc++) {
        const uint4 ah0 = *(const uint4*)&s_mA[kc * 128 + lane * 4];
        const uint4 al0 = *(const uint4*)&s_mAl[kc * 128 + lane * 4];
        const uint4 ah1 = *(const uint4*)&s_mA[(16 + kc) * 128 + lane * 4];
        const uint4 al1 = *(const uint4*)&s_mAl[(16 + kc) * 128 + lane * 4];
#pragma unroll
        for (int nt = 0; nt < 4; nt++) {
            const uint4 bf = __ldg(&g_awf2[(kc * 32 + 4 * w + nt) * 32 + lane]);
            hmma_bf16(acc[0][nt], ah0, bf.x, bf.y);
            hmma_bf16(acc[0][nt], ah0, bf.z, bf.w);
            hmma_bf16(acc[0][nt], al0, bf.x, bf.y);
            hmma_bf16(acc[1][nt], ah1, bf.x, bf.y);
            hmma_bf16(acc[1][nt], ah1, bf.z, bf.w);
            hmma_bf16(acc[1][nt], al1, bf.x, bf.y);
        }
    }

    // ---- layer 3 ----
    {
        float pc[2][2] = {{0.f, 0.f}, {0.f, 0.f}};
#pragma unroll
        for (int mt = 0; mt < 2; mt++)
#pragma unroll
            for (int nt = 0; nt < 4; nt++) {
                pc[mt][0] += tanhf(acc[mt][nt][0] + bj2v[nt][0]) * w3j[nt][0]
                           + tanhf(acc[mt][nt][1] + bj2v[nt][1]) * w3j[nt][1];
                pc[mt][1] += tanhf(acc[mt][nt][2] + bj2v[nt][0]) * w3j[nt][0]
                           + tanhf(acc[mt][nt][3] + bj2v[nt][1]) * w3j[nt][1];
            }
#pragma unroll
        for (int mt = 0; mt < 2; mt++)
#pragma unroll
            for (int rh = 0; rh < 2; rh++) {
                float v = pc[mt][rh];
                v += __shfl_xor_sync(0xffffffffu, v, 1);
                v += __shfl_xor_sync(0xffffffffu, v, 2);
                pc[mt][rh] = v;
            }
        if (tig == 0) {
            s_red[w * 32 + 0 * 16 + gid]     = pc[0][0];
            s_red[w * 32 + 0 * 16 + gid + 8] = pc[0][1];
            s_red[w * 32 + 1 * 16 + gid]     = pc[1][0];
            s_red[w * 32 + 1 * 16 + gid + 8] = pc[1][1];
        }
    }
    __syncthreads();
    if (tid < CC) {
        float s = ab3[0];
#pragma unroll
        for (int ww = 0; ww < 8; ww++) s += s_red[ww * 32 + tid];
        if (tid < nvalid) g_scores[b][c0 + tid] = s;
    }
}

// ---------------------------------------------------------------------------
// K3: critic + masked softmax (proven).
// ---------------------------------------------------------------------------
__global__ __launch_bounds__(256) void k_final(
    const unsigned char* __restrict__ mask,
    const float* __restrict__ cw1, const float* __restrict__ cb1,
    const float* __restrict__ cw2, const float* __restrict__ cb2,
    const float* __restrict__ cw3, const float* __restrict__ cb3,
    float* __restrict__ out)
{
    __shared__ float s_in[HA];
    __shared__ float s_hid[HA];
    __shared__ float s_r[8];
    __shared__ float s_b0, s_b1v;

    const int tid = threadIdx.x, b = blockIdx.x;
    const int lane = tid & 31, warp = tid >> 5;

    s_in[tid] = g_pooled[b][tid];
    __syncthreads();
    float acc = cb1[tid];
    for (int i = 0; i < HA; i++) acc = fmaf(s_in[i], cw1[i * HA + tid], acc);
    s_hid[tid] = tanhf(acc);
    __syncthreads();
    acc = cb2[tid];
    for (int i = 0; i < HA; i++) acc = fmaf(s_hid[i], cw2[i * HA + tid], acc);
    {
        float p = tanhf(acc) * cw3[tid];
        p += __shfl_xor_sync(0xffffffffu, p, 16);
        p += __shfl_xor_sync(0xffffffffu, p, 8);
        p += __shfl_xor_sync(0xffffffffu, p, 4);
        p += __shfl_xor_sync(0xffffffffu, p, 2);
        p += __shfl_xor_sync(0xffffffffu, p, 1);
        if (lane == 0) s_r[warp] = p;
    }
    __syncthreads();
    if (tid == 0) {
        float v = cb3[0];
#pragma unroll
        for (int w = 0; w < 8; w++) v += s_r[w];
        out[BATCH * NC + b] = v;
    }

    const int c = tid;
    bool valid = false;
    float s = -FLT_MAX;
    if (c < NC) {
        const int mi = b * NC + c;
        const int mv = g_mask_i32 ? ((const int*)mask)[mi] : (int)mask[mi];
        valid = (mv != 0);
        if (valid) s = g_scores[b][c];
    }
    float m = s;
    m = fmaxf(m, __shfl_xor_sync(0xffffffffu, m, 16));
    m = fmaxf(m, __shfl_xor_sync(0xffffffffu, m, 8));
    m = fmaxf(m, __shfl_xor_sync(0xffffffffu, m, 4));
    m = fmaxf(m, __shfl_xor_sync(0xffffffffu, m, 2));
    m = fmaxf(m, __shfl_xor_sync(0xffffffffu, m, 1));
    __syncthreads();
    if (lane == 0) s_r[warp] = m;
    __syncthreads();
    if (warp == 0) {
        float t = (lane < 8) ? s_r[lane] : -FLT_MAX;
        t = fmaxf(t, __shfl_xor_sync(0xffffffffu, t, 4));
        t = fmaxf(t, __shfl_xor_sync(0xffffffffu, t, 2));
        t = fmaxf(t, __shfl_xor_sync(0xffffffffu, t, 1));
        if (lane == 0) s_b0 = t;
    }
    __syncthreads();
    const float mx = s_b0;
    const float e = valid ? expf(s - mx) : 0.f;
    float se = e;
    se += __shfl_xor_sync(0xffffffffu, se, 16);
    se += __shfl_xor_sync(0xffffffffu, se, 8);
    se += __shfl_xor_sync(0xffffffffu, se, 4);
    se += __shfl_xor_sync(0xffffffffu, se, 2);
    se += __shfl_xor_sync(0xffffffffu, se, 1);
    __syncthreads();
    if (lane == 0) s_r[warp] = se;
    __syncthreads();
    if (warp == 0) {
        float t = (lane < 8) ? s_r[lane] : 0.f;
        t += __shfl_xor_sync(0xffffffffu, t, 4);
        t += __shfl_xor_sync(0xffffffffu, t, 2);
        t += __shfl_xor_sync(0xffffffffu, t, 1);
        if (lane == 0) s_b1v = t;
    }
    __syncthreads();
    if (c < NC) out[b * NC + c] = e / s_b1v;
}

// ---------------------------------------------------------------------------
extern "C" void kernel_launch(void* const* d_in, const int* in_sizes, int n_in,
                              void* d_out, int out_size)
{
    const float* x    = (const float*)d_in[0];
    const int*   cand = (const int*)d_in[1];
    const unsigned char* mask = (const unsigned char*)d_in[2];
    const float* fw1 = (const float*)d_in[3];
    const float* fb1 = (const float*)d_in[4];
    const float* fw2 = (const float*)d_in[5];
    const float* fb2 = (const float*)d_in[6];
    const float* aw1 = (const float*)d_in[7];
    const float* ab1 = (const float*)d_in[8];
    const float* aw2 = (const float*)d_in[9];
    const float* ab2 = (const float*)d_in[10];
    const float* aw3 = (const float*)d_in[11];
    const float* ab3 = (const float*)d_in[12];
    const float* cw1 = (const float*)d_in[13];
    const float* cb1 = (const float*)d_in[14];
    const float* cw2 = (const float*)d_in[15];
    const float* cb2 = (const float*)d_in[16];
    const float* cw3 = (const float*)d_in[17];
    const float* cb3 = (const float*)d_in[18];
    float* out = (float*)d_out;

    const int smem_fp = 16384 * (int)sizeof(uint32_t);   // 64KB (double-buffered)
    cudaFuncSetAttribute(k_featpool_wmma,
                         cudaFuncAttributeMaxDynamicSharedMemorySize, smem_fp);
    const int smem_actor = 14944 * (int)sizeof(uint32_t);   // 59776 B
    cudaFuncSetAttribute(k_actor_mma,
                         cudaFuncAttributeMaxDynamicSharedMemorySize, smem_actor);

    k_wsplit<<<96, 256>>>(aw1, aw2, mask);
    k_featpool_wmma<<<dim3(NCH, BATCH), 256, smem_fp>>>(x, fw1, fb1, fw2, fb2);
    k_pool<<<BATCH, HA>>>(aw1);
    k_actor_mma<<<dim3(NCHUNK, BATCH), 256, smem_actor>>>(
        x, cand, fw1, fb1, fw2, fb2, ab1, ab2, aw3, ab3);
    k_final<<<BATCH, 256>>>(mask, cw1, cb1, cw2, cb2, cw3, cb3, out);
}